// round 8
// baseline (speedup 1.0000x reference)
#include <cuda_runtime.h>
#include <cstdint>

// Problem constants (fixed by the reference)
#define B_DIM 1024
#define T_DIM 256
#define D_DIM 1024
#define NUM_LABELS 8
#define NUM_PROTOS 64   // per label; M = 512 total

#define FOLD_BLOCKS 64  // 8 labels x 8 d-segments of 128

// Device scratch (no cudaMalloc allowed). Zero-initialized at module load;
// the kernel self-resets g_done/g_exit at the end of every run, so no
// per-launch memset is needed (single-node graph).
__device__ float g_c[NUM_LABELS * D_DIM];  // c_l[d] = mean_p w[8p+l][d]  (32 KB)
__device__ float g_sq64[FOLD_BLOCKS];      // per (l,seg) partial sum of w^2
__device__ unsigned g_done = 0;            // fold-done counter
__device__ unsigned g_exit = 0;            // block-exit counter (for self-reset)

// ---------------------------------------------------------------------------
// Fused kernel, grid 1024 x 256. Block b streams batch row b.
// Blocks 0..63 run a ~1us COALESCED fold prologue first (hidden under the
// other 960 blocks' streaming):
//   block = (l = bid>>3, seg = bid&7); thread pair (tid>>1 = d-in-seg,
//   tid&1 = which 32 prototypes). 32 loads each, batched 16-wide, __ldcg.
//   Pair-combine via shfl_xor(1) (fp32 add commutative -> bit-exact both
//   lanes); block-reduce sq (each d counted twice; *0.5f exact scaling).
// Every block's epilogue spins on g_done==64 — satisfied ~150us earlier.
// Self-reset: the LAST block to finish (g_exit==1023) zeroes both counters;
// all other blocks have already passed their spin by then, and graph replays
// are stream-serialized, so the invariant holds across runs.
// ---------------------------------------------------------------------------
__global__ __launch_bounds__(256, 8)
void fused_pool_proto_kernel(const float* __restrict__ h,
                             const float* __restrict__ w,
                             float* __restrict__ out) {
    const int b    = blockIdx.x;
    const int tid  = threadIdx.x;
    const int wid  = tid >> 5;
    const int lane = tid & 31;
    const unsigned FULL = 0xFFFFFFFFu;

    // ---- Fold prologue (blocks 0..63 only) ----
    if (b < FOLD_BLOCKS) {
        const int l   = b >> 3;
        const int seg = b & 7;
        const int d   = seg * 128 + (tid >> 1);
        const int ph  = tid & 1;            // which half of the 64 prototypes

        float sum = 0.0f, sq = 0.0f;
#pragma unroll
        for (int pb = 0; pb < 32; pb += 16) {
            float v[16];
#pragma unroll
            for (int i = 0; i < 16; ++i)
                v[i] = __ldcg(&w[(size_t)(((ph * 32 + pb + i) << 3) + l) * D_DIM + d]);
#pragma unroll
            for (int i = 0; i < 16; ++i) {
                sum += v[i];
                sq  += v[i] * v[i];
            }
        }
        // Combine the two p-halves of this d (commutative -> identical on both lanes)
        sum += __shfl_xor_sync(FULL, sum, 1);
        sq  += __shfl_xor_sync(FULL, sq,  1);
        if (ph == 0) g_c[l * D_DIM + d] = sum * (1.0f / NUM_PROTOS);

        // Block-reduce sq over the 128 d's (each counted twice; fixed order)
#pragma unroll
        for (int off = 16; off > 0; off >>= 1)
            sq += __shfl_xor_sync(FULL, sq, off);
        __shared__ float red[8];
        if (lane == 0) red[wid] = sq;
        __syncthreads();
        if (tid == 0) {
            float t = 0.0f;
#pragma unroll
            for (int ww = 0; ww < 8; ++ww) t += red[ww];
            g_sq64[b] = t * 0.5f;           // undo the double count (exact)
            __threadfence();
            atomicAdd(&g_done, 1u);
        }
        __syncthreads();
    }

    // ---- Streaming phase (identical to the proven 154.9us loop) ----
    const float4* hp = reinterpret_cast<const float4*>(h)
                       + (size_t)b * T_DIM * (D_DIM / 4) + tid;

    float4 s0 = {0,0,0,0}, s1 = {0,0,0,0}, s2 = {0,0,0,0}, s3 = {0,0,0,0};
#pragma unroll 4
    for (int t = 0; t < T_DIM; t += 8) {
        float4 v0 = __ldcs(hp + (size_t)(t + 0) * 256);
        float4 v1 = __ldcs(hp + (size_t)(t + 1) * 256);
        float4 v2 = __ldcs(hp + (size_t)(t + 2) * 256);
        float4 v3 = __ldcs(hp + (size_t)(t + 3) * 256);
        float4 v4 = __ldcs(hp + (size_t)(t + 4) * 256);
        float4 v5 = __ldcs(hp + (size_t)(t + 5) * 256);
        float4 v6 = __ldcs(hp + (size_t)(t + 6) * 256);
        float4 v7 = __ldcs(hp + (size_t)(t + 7) * 256);
        s0.x += v0.x; s0.y += v0.y; s0.z += v0.z; s0.w += v0.w;
        s1.x += v1.x; s1.y += v1.y; s1.z += v1.z; s1.w += v1.w;
        s2.x += v2.x; s2.y += v2.y; s2.z += v2.z; s2.w += v2.w;
        s3.x += v3.x; s3.y += v3.y; s3.z += v3.z; s3.w += v3.w;
        s0.x += v4.x; s0.y += v4.y; s0.z += v4.z; s0.w += v4.w;
        s1.x += v5.x; s1.y += v5.y; s1.z += v5.z; s1.w += v5.w;
        s2.x += v6.x; s2.y += v6.y; s2.z += v6.z; s2.w += v6.w;
        s3.x += v7.x; s3.y += v7.y; s3.z += v7.z; s3.w += v7.w;
    }

    const float inv_t = 1.0f / T_DIM;
    float4 a;
    a.x = (s0.x + s1.x + s2.x + s3.x) * inv_t;
    a.y = (s0.y + s1.y + s2.y + s3.y) * inv_t;
    a.z = (s0.z + s1.z + s2.z + s3.z) * inv_t;
    a.w = (s0.w + s1.w + s2.w + s3.w) * inv_t;

    float asq = a.x * a.x + a.y * a.y + a.z * a.z + a.w * a.w;

    // ---- Wait for fold (satisfied ~150us ago -> first poll succeeds) ----
    if (tid == 0) {
        while (atomicAdd(&g_done, 0u) < (unsigned)FOLD_BLOCKS) {}
    }
    __syncthreads();
    __threadfence();

    // ---- Epilogue: 8 dots vs c_l + reductions ----
    float dot[NUM_LABELS];
#pragma unroll
    for (int l = 0; l < NUM_LABELS; ++l) {
        float4 cv = reinterpret_cast<const float4*>(g_c + l * D_DIM)[tid];
        dot[l] = a.x * cv.x + a.y * cv.y + a.z * cv.z + a.w * cv.w;
    }

#pragma unroll
    for (int off = 16; off > 0; off >>= 1) {
        asq += __shfl_xor_sync(FULL, asq, off);
#pragma unroll
        for (int l = 0; l < NUM_LABELS; ++l)
            dot[l] += __shfl_xor_sync(FULL, dot[l], off);
    }

    __shared__ float part[8][12];  // 8 warps x (8 dots + asq), padded
    if (lane == 0) {
#pragma unroll
        for (int l = 0; l < NUM_LABELS; ++l) part[wid][l] = dot[l];
        part[wid][8] = asq;
    }
    __syncthreads();

    if (tid < NUM_LABELS) {
        const int l = tid;
        float dl = 0.0f, aq = 0.0f;
#pragma unroll
        for (int ww = 0; ww < 8; ++ww) {
            dl += part[ww][l];
            aq += part[ww][8];
        }
        float sl = 0.0f;
#pragma unroll
        for (int seg = 0; seg < 8; ++seg) sl += g_sq64[l * 8 + seg];
        sl *= (1.0f / NUM_PROTOS);
        out[(size_t)b * NUM_LABELS + l] = 2.0f * dl - aq - sl;
    }

    // ---- Self-reset by the last block to finish ----
    __syncthreads();   // all threads of this block done with g_done/g_c reads
    if (tid == 0) {
        __threadfence();
        unsigned prev = atomicAdd(&g_exit, 1u);
        if (prev == (unsigned)(B_DIM - 1)) {
            // Every other block has passed its spin (they incremented g_exit
            // after it). Reset for the next graph replay.
            g_done = 0;
            g_exit = 0;
            __threadfence();
        }
    }
}

extern "C" void kernel_launch(void* const* d_in, const int* in_sizes, int n_in,
                              void* d_out, int out_size) {
    const float* h = (const float*)d_in[0];   // hidden_states [B, T, D]
    const float* w = (const float*)d_in[1];   // prototype_weight [512, D]
    float* out = (float*)d_out;               // [B, 8]

    // Single-node graph: flags are self-resetting (zeroed at module load,
    // re-zeroed by the last exiting block each run).
    fused_pool_proto_kernel<<<B_DIM, 256>>>(h, w, out);
}